// round 3
// baseline (speedup 1.0000x reference)
#include <cuda_runtime.h>
#include <cstdint>

#define T_LEN 16384
#define NXD 128
#define NHD 512
#define STEPS (T_LEN - NXD)   /* 16256 */
#define NGC (NHD * 4)         /* 2048 */

// h history: per (t,j) one u64 = (tag = t+1) << 32 | float bits of h
__device__ unsigned long long g_h64[(size_t)STEPS * NHD];   // 66 MB
// gate pre-activations, interleaved (f,i,o,c) per (t,j)
__device__ float4 g_gate4[(size_t)STEPS * NHD];             // 133 MB

__device__ __forceinline__ void ld_rlx2(const unsigned long long* p,
                                        unsigned long long& a, unsigned long long& b) {
    asm volatile("ld.relaxed.gpu.global.v2.u64 {%0,%1}, [%2];"
                 : "=l"(a), "=l"(b) : "l"(p) : "memory");
}
__device__ __forceinline__ void st_rlx(unsigned long long* p, unsigned long long v) {
    asm volatile("st.relaxed.gpu.global.u64 [%0], %1;" :: "l"(p), "l"(v) : "memory");
}
__device__ __forceinline__ float tanh_hw(float x) {
    float y;
    asm("tanh.approx.f32 %0, %1;" : "=f"(y) : "f"(x));
    return y;
}
__device__ __forceinline__ float sigm(float x) {
    return fmaf(tanh_hw(0.5f * x), 0.5f, 0.5f);
}
__device__ __forceinline__ unsigned long long pack2(float lo, float hi) {
    unsigned long long r;
    asm("mov.b64 %0, {%1, %2};" : "=l"(r) : "f"(lo), "f"(hi));
    return r;
}
__device__ __forceinline__ void fma2(unsigned long long& d,
                                     unsigned long long a, unsigned long long b) {
    asm("fma.rn.f32x2 %0, %1, %2, %0;" : "+l"(d) : "l"(a), "l"(b));
}
__device__ __forceinline__ float hsum2(unsigned long long v) {
    float lo, hi;
    asm("mov.b64 {%0, %1}, %2;" : "=f"(lo), "=f"(hi) : "l"(v));
    return lo + hi;
}

// ---------------------------------------------------------------------------
// Clear tags (runs at END of each call; device globals are zero-init for call 1)
// ---------------------------------------------------------------------------
__global__ void zero_kernel() {
    int idx = blockIdx.x * blockDim.x + threadIdx.x;
    int stride = gridDim.x * blockDim.x;
    for (int i = idx; i < STEPS * NHD; i += stride) g_h64[i] = 0ull;
}

// ---------------------------------------------------------------------------
// Gate pre-activation GEMM: gate[t][c] = b + sum_k W[c][k] * x[t+k]
// ---------------------------------------------------------------------------
__global__ void precompute_kernel(const float* __restrict__ x,
                                  const float* __restrict__ Wf, const float* __restrict__ bf,
                                  const float* __restrict__ Wi, const float* __restrict__ bi,
                                  const float* __restrict__ Wo, const float* __restrict__ bo,
                                  const float* __restrict__ Wc, const float* __restrict__ bc) {
    __shared__ float xs[192];
    __shared__ float Ws[128][65];
    const int tBase = blockIdx.x * 64;
    const int cBase = blockIdx.y * 64;
    const int tid = threadIdx.x;

    for (int i = tid; i < 191; i += 256) xs[i] = x[tBase + i];
    for (int idx = tid; idx < 8192; idx += 256) {
        int r = idx >> 7, k = idx & 127;
        int c = cBase + r;
        int j = c >> 2, g = c & 3;
        const float* W = (g == 0) ? Wf : (g == 1) ? Wi : (g == 2) ? Wo : Wc;
        Ws[k][r] = W[j * NXD + k];
    }
    __syncthreads();

    const int tx = tid & 15, ty = tid >> 4;
    const int t0 = ty * 4, r0 = tx * 4;
    float acc[4][4] = {};
#pragma unroll 4
    for (int k = 0; k < 128; k++) {
        float a0 = xs[t0 + 0 + k], a1 = xs[t0 + 1 + k];
        float a2 = xs[t0 + 2 + k], a3 = xs[t0 + 3 + k];
        float b0 = Ws[k][r0 + 0], b1 = Ws[k][r0 + 1];
        float b2 = Ws[k][r0 + 2], b3 = Ws[k][r0 + 3];
        acc[0][0] += a0 * b0; acc[0][1] += a0 * b1; acc[0][2] += a0 * b2; acc[0][3] += a0 * b3;
        acc[1][0] += a1 * b0; acc[1][1] += a1 * b1; acc[1][2] += a1 * b2; acc[1][3] += a1 * b3;
        acc[2][0] += a2 * b0; acc[2][1] += a2 * b1; acc[2][2] += a2 * b2; acc[2][3] += a2 * b3;
        acc[3][0] += a3 * b0; acc[3][1] += a3 * b1; acc[3][2] += a3 * b2; acc[3][3] += a3 * b3;
    }
    float* out = reinterpret_cast<float*>(g_gate4);
#pragma unroll
    for (int ti = 0; ti < 4; ti++) {
#pragma unroll
        for (int cj = 0; cj < 4; cj++) {
            int t = tBase + t0 + ti;
            int c = cBase + r0 + cj;
            int j = c >> 2, g = c & 3;
            float bias = (g == 0) ? bf[j] : (g == 1) ? bi[j] : (g == 2) ? bo[j] : bc[j];
            out[(size_t)t * NGC + c] = acc[ti][cj] + bias;
        }
    }
}

// ---------------------------------------------------------------------------
// Persistent self-synchronizing recurrence.
// 128 CTAs x 256 threads. CTA b owns outputs j = 4b..4b+3.
// Warp w (0..7): output jj = w>>1, half = w&1 of the 512-dot (256 inputs).
// Lane l handles h indices half*256 + m*128 + l*4 .. +3 (m=0,1): conflict-free
// LDS.128 and packed f32x2 FMAs. U rows live in registers as f32 pairs.
// h exchange via relaxed tagged u64 in L2; each thread polls one 16B pair.
// ---------------------------------------------------------------------------
__global__ void __launch_bounds__(256, 1)
lstm_rec_kernel(const float* __restrict__ Uf, const float* __restrict__ Ui,
                const float* __restrict__ Uo, const float* __restrict__ Uc) {
    __shared__ float hs[2][NHD];
    __shared__ float part[4][4];   // [jj][gate] partial from odd-half warp

    const int tid = threadIdx.x;
    const int w = tid >> 5, l = tid & 31;
    const int jj = w >> 1, half = w & 1;
    const int j = blockIdx.x * 4 + jj;
    const bool leader = (half == 0) && (l == 0);

    // U pairs: u2[g][m*2+p] covers h indices half*256 + m*128 + l*4 + 2p..+1
    unsigned long long u2[4][4];
    {
        const float* Us[4] = {Uf, Ui, Uo, Uc};
#pragma unroll
        for (int g = 0; g < 4; g++) {
#pragma unroll
            for (int m = 0; m < 2; m++) {
                float4 q = *reinterpret_cast<const float4*>(
                    Us[g] + j * NHD + half * 256 + m * 128 + l * 4);
                u2[g][m * 2 + 0] = pack2(q.x, q.y);
                u2[g][m * 2 + 1] = pack2(q.z, q.w);
            }
        }
    }

    float cst = 0.f;
    float4 gx = make_float4(0.f, 0.f, 0.f, 0.f);
    if (leader) gx = g_gate4[j];   // gate inputs for t = 0

    for (int t = 0; t < STEPS; t++) {
        float* hb = hs[t & 1];
        if (t == 0) {
            hb[2 * tid] = 0.f;
            hb[2 * tid + 1] = 0.f;
        } else {
            const unsigned long long* src = g_h64 + (size_t)(t - 1) * NHD + 2 * tid;
            const unsigned tt = (unsigned)t;
            unsigned long long v0, v1;
            ld_rlx2(src, v0, v1);
            while ((unsigned)(v0 >> 32) != tt || (unsigned)(v1 >> 32) != tt)
                ld_rlx2(src, v0, v1);
            hb[2 * tid]     = __uint_as_float((unsigned)v0);
            hb[2 * tid + 1] = __uint_as_float((unsigned)v1);
        }
        __syncthreads();

        // packed h for this lane's slice
        const ulonglong2 hA = *reinterpret_cast<const ulonglong2*>(hb + half * 256 + 0   + l * 4);
        const ulonglong2 hB = *reinterpret_cast<const ulonglong2*>(hb + half * 256 + 128 + l * 4);

        float a[4];
#pragma unroll
        for (int g = 0; g < 4; g++) {
            unsigned long long acc = 0ull;   // (+0.f, +0.f)
            fma2(acc, u2[g][0], hA.x);
            fma2(acc, u2[g][1], hA.y);
            fma2(acc, u2[g][2], hB.x);
            fma2(acc, u2[g][3], hB.y);
            a[g] = hsum2(acc);
        }

#pragma unroll
        for (int off = 16; off; off >>= 1) {
            a[0] += __shfl_down_sync(0xffffffffu, a[0], off);
            a[1] += __shfl_down_sync(0xffffffffu, a[1], off);
            a[2] += __shfl_down_sync(0xffffffffu, a[2], off);
            a[3] += __shfl_down_sync(0xffffffffu, a[3], off);
        }

        if (half == 1 && l == 0)
            *reinterpret_cast<float4*>(&part[jj][0]) = make_float4(a[0], a[1], a[2], a[3]);
        __syncthreads();

        if (leader) {
            float4 pb = *reinterpret_cast<float4*>(&part[jj][0]);
            float f = sigm(gx.x + a[0] + pb.x);
            float i = sigm(gx.y + a[1] + pb.y);
            float o = sigm(gx.z + a[2] + pb.z);
            float g = tanh_hw(gx.w + a[3] + pb.w);
            cst = f * cst + i * g;
            float h = o * tanh_hw(cst);
            st_rlx(g_h64 + (size_t)t * NHD + j,
                   ((unsigned long long)(unsigned)(t + 1) << 32) |
                   (unsigned long long)__float_as_uint(h));
            if (t + 1 < STEPS) gx = g_gate4[(size_t)(t + 1) * NHD + j];  // prefetch
        }
    }
}

// ---------------------------------------------------------------------------
// mu epilogue: out[t] = by + sum_j Ahy[j] * h[t][j]   (one warp per t)
// ---------------------------------------------------------------------------
__global__ void mu_kernel(const float* __restrict__ Ahy, const float* __restrict__ by,
                          float* __restrict__ out) {
    int gw = (int)((blockIdx.x * blockDim.x + threadIdx.x) >> 5);
    int l = threadIdx.x & 31;
    if (gw >= STEPS) return;
    const unsigned long long* hrow = g_h64 + (size_t)gw * NHD;
    float s = 0.f;
#pragma unroll
    for (int m = 0; m < 16; m++) {
        int idx = l + 32 * m;
        s += Ahy[idx] * __uint_as_float((unsigned)hrow[idx]);
    }
#pragma unroll
    for (int off = 16; off; off >>= 1) s += __shfl_down_sync(0xffffffffu, s, off);
    if (l == 0) out[gw] = s + by[0];
}

// ---------------------------------------------------------------------------
// Launch order [precompute, lstm, mu, zero]:
//  - zero at the END prepares tags for the NEXT replay (globals zero-init for call 1)
//  - puts lstm_rec at global launch index 6 so ncu (-s 5 -c 1) profiles it
// ---------------------------------------------------------------------------
extern "C" void kernel_launch(void* const* d_in, const int* in_sizes, int n_in,
                              void* d_out, int out_size) {
    const float* x   = (const float*)d_in[0];
    const float* Wf  = (const float*)d_in[1];
    const float* Uf  = (const float*)d_in[2];
    const float* bf  = (const float*)d_in[3];
    const float* Wi  = (const float*)d_in[4];
    const float* Ui  = (const float*)d_in[5];
    const float* bi  = (const float*)d_in[6];
    const float* Wo  = (const float*)d_in[7];
    const float* Uo  = (const float*)d_in[8];
    const float* bo  = (const float*)d_in[9];
    const float* Wc  = (const float*)d_in[10];
    const float* Uc  = (const float*)d_in[11];
    const float* bc  = (const float*)d_in[12];
    const float* Ahy = (const float*)d_in[13];
    const float* by  = (const float*)d_in[14];
    float* out = (float*)d_out;

    precompute_kernel<<<dim3(STEPS / 64, NGC / 64), 256>>>(x, Wf, bf, Wi, bi, Wo, bo, Wc, bc);
    lstm_rec_kernel<<<NHD / 4, 256>>>(Uf, Ui, Uo, Uc);
    mu_kernel<<<(STEPS * 32 + 127) / 128, 128>>>(Ahy, by, out);
    zero_kernel<<<1024, 256>>>();
    (void)in_sizes; (void)n_in; (void)out_size;
}